// round 7
// baseline (speedup 1.0000x reference)
#include <cuda_runtime.h>

// MutualProjection: B=8, V=4, J=21, IMG=128
// Ball-centric rasterization: 1 CTA per image, image staged in smem as
// order-encoded uint32, atomicMin scatter, single vectorized writeback.

#define IMG   128
#define BIGV  1000000.0f
#define B_    8
#define V_    4
#define J_    21
#define NTHR  512
#define NPIX  (IMG * IMG)

__device__ __forceinline__ float fsqrt_approx(float a) {
    float r;
    asm("sqrt.approx.f32 %0, %1;" : "=f"(r) : "f"(a));
    return r;
}

// Monotone float->uint transform (total order, works for negatives):
//   a <= b  <=>  enc(a) <= enc(b)
__device__ __forceinline__ unsigned enc_f(float f) {
    unsigned u = __float_as_uint(f);
    return (u & 0x80000000u) ? ~u : (u | 0x80000000u);
}
__device__ __forceinline__ float dec_f(unsigned u) {
    return (u & 0x80000000u) ? __uint_as_float(u ^ 0x80000000u)
                             : __uint_as_float(~u);
}

__global__ __launch_bounds__(NTHR)
void mutual_projection_kernel(
    const float* __restrict__ cam,     // (B,V,4,4)
    const float* __restrict__ inv,     // (B,V,4,4)
    const float* __restrict__ joints,  // (B,V,J,3)
    const float* __restrict__ rads,    // (J)
    float* __restrict__ depth_out,     // (B,V,V,128,128)
    float* __restrict__ proj_out)      // (B,V,V,J,3)
{
    extern __shared__ unsigned simg[];   // NPIX words = 64 KB (dynamic)
    __shared__ float4 ball[J_];          // {px, py, pz, r2}
    __shared__ int4   bb[J_];            // {x0, width, y0, height}

    const int blk  = blockIdx.x;         // image index
    const int b    = blk >> 4;
    const int i    = (blk >> 2) & 3;
    const int j    = blk & 3;
    const int t    = threadIdx.x;
    const int w    = t >> 5;
    const int lane = t & 31;
    const unsigned FULL = 0xFFFFFFFFu;

    if (w == 0) {
        // ---- setup warp: mutual matrix, projections, bboxes ----
        const float* camM = cam + ((b * V_ + i) << 4);
        const float* invM = inv + ((b * V_ + j) << 4);

        float acc = 0.0f;
        if (lane < 12) {
            const int xr = lane >> 2, z = lane & 3;
            acc =              invM[xr * 4 + 0] * camM[0 * 4 + z];
            acc = fmaf(invM[xr * 4 + 1], camM[1 * 4 + z], acc);
            acc = fmaf(invM[xr * 4 + 2], camM[2 * 4 + z], acc);
            acc = fmaf(invM[xr * 4 + 3], camM[3 * 4 + z], acc);
        }
        const float m0  = __shfl_sync(FULL, acc, 0);
        const float m1  = __shfl_sync(FULL, acc, 1);
        const float m2  = __shfl_sync(FULL, acc, 2);
        const float m3  = __shfl_sync(FULL, acc, 3);
        const float m4  = __shfl_sync(FULL, acc, 4);
        const float m5  = __shfl_sync(FULL, acc, 5);
        const float m6  = __shfl_sync(FULL, acc, 6);
        const float m7  = __shfl_sync(FULL, acc, 7);
        const float m8  = __shfl_sync(FULL, acc, 8);
        const float m9  = __shfl_sync(FULL, acc, 9);
        const float m10 = __shfl_sync(FULL, acc, 10);
        const float m11 = __shfl_sync(FULL, acc, 11);

        if (lane < J_) {
            const float* jp = joints + ((b * V_ + i) * J_ + lane) * 3;
            const float jx = jp[0], jy = jp[1], jz = jp[2];
            const float qx = fmaf(m2,  jz, fmaf(m1, jy, m0 * jx)) + m3;
            const float qy = fmaf(m6,  jz, fmaf(m5, jy, m4 * jx)) + m7;
            const float qz = fmaf(m10, jz, fmaf(m9, jy, m8 * jx)) + m11;
            const float r  = rads[lane];
            const float r2 = r * r;

            float* po = proj_out + (blk * J_ + lane) * 3;
            po[0] = qx; po[1] = qy; po[2] = qz;

            ball[lane] = make_float4(qx, qy, qz, r2);

            // Conservative bbox (floor/ceil widen by <=1 px each side; inside
            // test d2<r2 rejects the extras, so no false positives possible).
            int x0 = max(0,       (int)floorf(qx - r));
            int x1 = min(IMG - 1, (int)ceilf (qx + r));
            int y0 = max(0,       (int)floorf(qy - r));
            int y1 = min(IMG - 1, (int)ceilf (qy + r));
            int bw = max(0, x1 - x0 + 1);
            int bh = max(0, y1 - y0 + 1);
            bb[lane] = make_int4(x0, bw, y0, bh);
        }
    } else {
        // ---- warps 1..15: init image to enc(BIG) ----
        const unsigned EB = 0x80000000u | __float_as_uint(BIGV);
        uint4* p4 = (uint4*)simg;
        const uint4 ev = make_uint4(EB, EB, EB, EB);
        for (int idx = t - 32; idx < NPIX / 4; idx += NTHR - 32) p4[idx] = ev;
    }
    __syncthreads();

    // ---- ball scatter: each thread tests one bbox pixel per ball ----
    for (int k = 0; k < J_; k++) {
        const int4 box  = bb[k];
        const int  area = box.y * box.w;
        if (t < area) {
            const float4 p = ball[k];
            const int yy = box.z + t / box.y;
            const int xx = box.x + (t - (t / box.y) * box.y);
            const float dx = __fsub_rn((float)xx, p.x);
            const float dy = __fsub_rn((float)yy, p.y);
            const float d2 = __fadd_rn(__fmul_rn(dx, dx), __fmul_rn(dy, dy));
            if (d2 < p.w) {
                const float v = p.z - fsqrt_approx(p.w - d2);
                atomicMin(&simg[yy * IMG + xx], enc_f(v));
            }
        }
    }
    __syncthreads();

    // ---- writeback: decode + STG.128 ----
    float4*      dst = (float4*)(depth_out + (size_t)blk * NPIX);
    const uint4* src = (const uint4*)simg;
    for (int idx = t; idx < NPIX / 4; idx += NTHR) {
        const uint4 u = src[idx];
        dst[idx] = make_float4(dec_f(u.x), dec_f(u.y), dec_f(u.z), dec_f(u.w));
    }
}

extern "C" void kernel_launch(void* const* d_in, const int* in_sizes, int n_in,
                              void* d_out, int out_size)
{
    const float* cam    = (const float*)d_in[0];
    const float* inv    = (const float*)d_in[1];
    const float* joints = (const float*)d_in[2];
    const float* rads   = (const float*)d_in[3];

    float* depth = (float*)d_out;                                // 8*4*4*128*128
    float* proj  = depth + (size_t)B_ * V_ * V_ * IMG * IMG;     // + 8*4*4*21*3

    static int smem_set = 0;
    if (!smem_set) {
        cudaFuncSetAttribute(mutual_projection_kernel,
                             cudaFuncAttributeMaxDynamicSharedMemorySize,
                             NPIX * 4);
        smem_set = 1;
    }
    mutual_projection_kernel<<<B_ * V_ * V_, NTHR, NPIX * 4>>>(
        cam, inv, joints, rads, depth, proj);
}

// round 8
// speedup vs baseline: 1.0058x; 1.0058x over previous
#include <cuda_runtime.h>

// MutualProjection: B=8, V=4, J=21, IMG=128
// out = [depth_imgs (B,V,V,128,128) f32][proj (B,V,V,J,3,1) f32]
//
// Warp tile = 128 cols x 2 rows; thread = 4 consecutive cols x 2 rows.
// Tight 2-row row-cull + 4-col per-thread col-cull + STG.128 stores.

#define IMG   128
#define BIGV  1000000.0f
#define B_    8
#define V_    4
#define J_    21
#define SPLIT 8                  // CTAs per image; CTA = 16 rows = 8 warp rows

__device__ __forceinline__ float fsqrt_approx(float a) {
    float r;
    asm("sqrt.approx.f32 %0, %1;" : "=f"(r) : "f"(a));
    return r;
}

__global__ __launch_bounds__(256)
void mutual_projection_kernel(
    const float* __restrict__ cam,     // (B,V,4,4)
    const float* __restrict__ inv,     // (B,V,4,4)
    const float* __restrict__ joints,  // (B,V,J,3)
    const float* __restrict__ rads,    // (J)
    float* __restrict__ depth_out,     // (B,V,V,128,128)
    float* __restrict__ proj_out)      // (B,V,V,J,3)
{
    __shared__ float4 ball[J_];        // {qx, qy, qz, r2}
    __shared__ float  rs_s[J_];        // r  (row-cull threshold base)
    __shared__ float  rc2_s[J_];       // (r + 1.51)^2  (col-cull threshold)
    __shared__ float4 wball[8][J_];    // per-warp compacted survivors
    __shared__ float  wrc2[8][J_];     // matching col thresholds

    const int blk  = blockIdx.x >> 3;  // image index in [0,128)
    const int s    = blockIdx.x & 7;   // 16-row slab
    const int b    = blk >> 4;
    const int i    = (blk >> 2) & 3;
    const int j    = blk & 3;
    const int t    = threadIdx.x;
    const int w    = t >> 5;
    const int lane = t & 31;
    const unsigned FULL = 0xFFFFFFFFu;

    // ---- warp 0: mutual matrix + projections into smem ----
    if (w == 0) {
        const float* camM = cam + ((b * V_ + i) << 4);
        const float* invM = inv + ((b * V_ + j) << 4);

        float acc = 0.0f;
        if (lane < 12) {
            const int xr = lane >> 2, z = lane & 3;
            acc =              invM[xr * 4 + 0] * camM[0 * 4 + z];
            acc = fmaf(invM[xr * 4 + 1], camM[1 * 4 + z], acc);
            acc = fmaf(invM[xr * 4 + 2], camM[2 * 4 + z], acc);
            acc = fmaf(invM[xr * 4 + 3], camM[3 * 4 + z], acc);
        }
        const float m0  = __shfl_sync(FULL, acc, 0);
        const float m1  = __shfl_sync(FULL, acc, 1);
        const float m2  = __shfl_sync(FULL, acc, 2);
        const float m3  = __shfl_sync(FULL, acc, 3);
        const float m4  = __shfl_sync(FULL, acc, 4);
        const float m5  = __shfl_sync(FULL, acc, 5);
        const float m6  = __shfl_sync(FULL, acc, 6);
        const float m7  = __shfl_sync(FULL, acc, 7);
        const float m8  = __shfl_sync(FULL, acc, 8);
        const float m9  = __shfl_sync(FULL, acc, 9);
        const float m10 = __shfl_sync(FULL, acc, 10);
        const float m11 = __shfl_sync(FULL, acc, 11);

        if (lane < J_) {
            const float* jp = joints + ((b * V_ + i) * J_ + lane) * 3;
            const float jx = jp[0], jy = jp[1], jz = jp[2];
            const float qx = fmaf(m2,  jz, fmaf(m1, jy, m0 * jx)) + m3;
            const float qy = fmaf(m6,  jz, fmaf(m5, jy, m4 * jx)) + m7;
            const float qz = fmaf(m10, jz, fmaf(m9, jy, m8 * jx)) + m11;
            const float r  = rads[lane];
            ball[lane]  = make_float4(qx, qy, qz, r * r);
            rs_s[lane]  = r;
            const float rc = r + 1.51f;
            rc2_s[lane] = rc * rc;
            if (s == 0) {
                float* po = proj_out + (blk * J_ + lane) * 3;
                po[0] = qx; po[1] = qy; po[2] = qz;
            }
        }
    }
    __syncthreads();

    // ---- per-warp row cull for its 2-row band; ballot-compact ----
    const int y0 = (s << 4) + (w << 1);         // first of 2 rows
    bool pass = false;
    float4 p4;
    float  rc2v = 0.0f;
    if (lane < J_) {
        p4   = ball[lane];
        rc2v = rc2_s[lane];
        const float yc = (float)y0 + 0.5f;      // exact
        // +0.01 safety: rounding can never cull a true-inside pixel
        pass = fabsf(p4.y - yc) < rs_s[lane] + 0.51f;
    }
    const unsigned mask = __ballot_sync(FULL, pass);
    const int cnt = __popc(mask);               // warp-uniform, in registers
    if (pass) {
        const int pos = __popc(mask & ((1u << lane) - 1u));
        wball[w][pos] = p4;
        wrc2[w][pos]  = rc2v;
    }
    __syncwarp(FULL);

    // ---- rasterize: thread owns cols x0..x0+3, rows y0, y0+1 ----
    const int   x0  = lane << 2;
    const float xcf = (float)x0 + 1.5f;         // 4-col span center (exact)
    const float y0f = (float)y0;

    float4 best0 = make_float4(BIGV, BIGV, BIGV, BIGV);
    float4 best1 = make_float4(BIGV, BIGV, BIGV, BIGV);

    for (int n = 0; n < cnt; n++) {
        const float4 p   = wball[w][n];
        const float  dxc = __fsub_rn(xcf, p.x);
        // conservative col cull: skip only if all 4 columns provably miss
        if (__fmul_rn(dxc, dxc) >= wrc2[w][n]) continue;

        const float dy0 = __fsub_rn(y0f, p.y);
        const float dy1 = __fsub_rn(y0f + 1.0f, p.y);
        const float dy0sq = __fmul_rn(dy0, dy0);
        const float dy1sq = __fmul_rn(dy1, dy1);

        float* b0 = &best0.x;
        float* b1 = &best1.x;
#pragma unroll
        for (int c = 0; c < 4; c++) {
            const float xf  = (float)(x0 + c);               // exact
            const float dx  = __fsub_rn(xf, p.x);
            const float dx2 = __fmul_rn(dx, dx);

            const float d2a  = __fadd_rn(dx2, dy0sq);
            const float arga = __fsub_rn(p.w, d2a);          // >0 <=> d2a < r2 (sign-exact)
            const float va   = p.z - fsqrt_approx(arga);
            if (arga > 0.0f) b0[c] = fminf(b0[c], va);

            const float d2b  = __fadd_rn(dx2, dy1sq);
            const float argb = __fsub_rn(p.w, d2b);
            const float vb   = p.z - fsqrt_approx(argb);
            if (argb > 0.0f) b1[c] = fminf(b1[c], vb);
        }
    }

    float* base = depth_out + blk * (IMG * IMG) + y0 * IMG + x0;
    *(float4*)(base)       = best0;
    *(float4*)(base + IMG) = best1;
}

extern "C" void kernel_launch(void* const* d_in, const int* in_sizes, int n_in,
                              void* d_out, int out_size)
{
    const float* cam    = (const float*)d_in[0];
    const float* inv    = (const float*)d_in[1];
    const float* joints = (const float*)d_in[2];
    const float* rads   = (const float*)d_in[3];

    float* depth = (float*)d_out;                                // 8*4*4*128*128
    float* proj  = depth + (size_t)B_ * V_ * V_ * IMG * IMG;     // + 8*4*4*21*3

    const int grid = B_ * V_ * V_ * SPLIT;   // 1024
    mutual_projection_kernel<<<grid, 256>>>(cam, inv, joints, rads, depth, proj);
}

// round 9
// speedup vs baseline: 1.2366x; 1.2294x over previous
#include <cuda_runtime.h>

// MutualProjection: B=8, V=4, J=21, IMG=128
// out = [depth_imgs (B,V,V,128,128) f32][proj (B,V,V,J,3,1) f32]
// R4 skeleton (best measured) + ball-loop unroll x2 for LDS-latency ILP.

#define IMG     128
#define BIGV    1000000.0f
#define B_      8
#define V_      4
#define J_      21
#define SPLIT   8                 // row-bands per image (16 rows per CTA)
#define RPT     8                 // consecutive rows per thread

__device__ __forceinline__ float fsqrt_approx(float a) {
    float r;
    asm("sqrt.approx.f32 %0, %1;" : "=f"(r) : "f"(a));
    return r;
}

__global__ __launch_bounds__(256)
void mutual_projection_kernel(
    const float* __restrict__ cam,     // (B,V,4,4)
    const float* __restrict__ inv,     // (B,V,4,4)
    const float* __restrict__ joints,  // (B,V,J,3)
    const float* __restrict__ rads,    // (J)
    float* __restrict__ depth_out,     // (B,V,V,128,128)
    float* __restrict__ proj_out)      // (B,V,V,J,3)
{
    __shared__ float4 blist[2][J_];    // per-band compacted {px,py,pz,r2}
    __shared__ int    bcnt[2];

    const int blk = blockIdx.x >> 3;   // image index in [0,128)
    const int s   = blockIdx.x & 7;    // 16-row band
    const int b   = blk >> 4;
    const int i   = (blk >> 2) & 3;
    const int j   = blk & 3;
    const int t   = threadIdx.x;
    const int w   = t >> 5;
    const int lane = t & 31;

    // ---- Prologue: warps 0 and 1 each build the compacted ball list for
    //      their band using only intra-warp communication. One CTA barrier.
    if (w < 2) {
        const float* camM = cam + ((b * V_ + i) << 4);
        const float* invM = inv + ((b * V_ + j) << 4);

        // lanes 0..11: M[x][z] = sum_y inv[j][x][y] * cam[i][y][z]
        float acc = 0.0f;
        if (lane < 12) {
            const int x = lane >> 2, z = lane & 3;
            acc =              invM[x * 4 + 0] * camM[0 * 4 + z];
            acc = fmaf(invM[x * 4 + 1], camM[1 * 4 + z], acc);
            acc = fmaf(invM[x * 4 + 2], camM[2 * 4 + z], acc);
            acc = fmaf(invM[x * 4 + 3], camM[3 * 4 + z], acc);
        }
        const unsigned FULL = 0xFFFFFFFFu;
        const float m0  = __shfl_sync(FULL, acc, 0);
        const float m1  = __shfl_sync(FULL, acc, 1);
        const float m2  = __shfl_sync(FULL, acc, 2);
        const float m3  = __shfl_sync(FULL, acc, 3);
        const float m4  = __shfl_sync(FULL, acc, 4);
        const float m5  = __shfl_sync(FULL, acc, 5);
        const float m6  = __shfl_sync(FULL, acc, 6);
        const float m7  = __shfl_sync(FULL, acc, 7);
        const float m8  = __shfl_sync(FULL, acc, 8);
        const float m9  = __shfl_sync(FULL, acc, 9);
        const float m10 = __shfl_sync(FULL, acc, 10);
        const float m11 = __shfl_sync(FULL, acc, 11);

        // lanes 0..20: project joint, row-cull for this warp's band, compact.
        bool pass = false;
        float qx = 0.f, qy = 0.f, qz = 0.f, r2 = 0.f;
        if (lane < J_) {
            const float* jp = joints + ((b * V_ + i) * J_ + lane) * 3;
            const float jx = jp[0], jy = jp[1], jz = jp[2];
            qx = fmaf(m2,  jz, fmaf(m1, jy, m0 * jx)) + m3;
            qy = fmaf(m6,  jz, fmaf(m5, jy, m4 * jx)) + m7;
            qz = fmaf(m10, jz, fmaf(m9, jy, m8 * jx)) + m11;
            const float r = rads[lane];
            r2 = r * r;
            if (w == 0 && s == 0) {
                float* po = proj_out + (blk * J_ + lane) * 3;
                po[0] = qx; po[1] = qy; po[2] = qz;
            }
            // band center = y0 + 3.5; +0.01 safety so rounding never culls
            // a true-inside pixel.
            const float yc = (float)(s * 16 + w * 8) + 3.5f;
            pass = fabsf(qy - yc) < r + 3.51f;
        }
        const unsigned mask = __ballot_sync(FULL, pass);
        if (pass) {
            const int pos = __popc(mask & ((1u << lane) - 1u));
            blist[w][pos] = make_float4(qx, qy, qz, r2);
        }
        if (lane == 0) bcnt[w] = __popc(mask);
    }
    __syncthreads();

    // ---- Rasterize: warp tile = 32 cols x 8 consecutive rows.
    const int tb  = w >> 2;                    // band within CTA
    const int x   = ((w & 3) << 5) | lane;
    const int y0  = (s << 4) + (tb << 3);
    const float xf  = (float)x;
    const float y0f = (float)y0;

    float best[RPT];
#pragma unroll
    for (int q = 0; q < RPT; q++) best[q] = BIGV;

    const int cnt = bcnt[tb];
    int n = 0;
    // Unroll x2: both LDS.128 issue before either body -> two independent
    // dependency chains, halving exposed shared-load latency per ball.
    for (; n + 1 < cnt; n += 2) {
        const float4 p0 = blist[tb][n];
        const float4 p1 = blist[tb][n + 1];

        const float dxa  = __fsub_rn(xf, p0.x);
        const float dx2a = __fmul_rn(dxa, dxa);
        const float dxb  = __fsub_rn(xf, p1.x);
        const float dx2b = __fmul_rn(dxb, dxb);

        if (dx2a < p0.w) {
#pragma unroll
            for (int q = 0; q < RPT; q++) {
                const float yf = y0f + (float)q;
                const float dy = __fsub_rn(yf, p0.y);
                const float d2 = __fadd_rn(dx2a, __fmul_rn(dy, dy));
                const float v  = p0.z - fsqrt_approx(p0.w - d2);
                if (d2 < p0.w) best[q] = fminf(best[q], v);
            }
        }
        if (dx2b < p1.w) {
#pragma unroll
            for (int q = 0; q < RPT; q++) {
                const float yf = y0f + (float)q;
                const float dy = __fsub_rn(yf, p1.y);
                const float d2 = __fadd_rn(dx2b, __fmul_rn(dy, dy));
                const float v  = p1.z - fsqrt_approx(p1.w - d2);
                if (d2 < p1.w) best[q] = fminf(best[q], v);
            }
        }
    }
    if (n < cnt) {
        const float4 p  = blist[tb][n];
        const float dx  = __fsub_rn(xf, p.x);
        const float dx2 = __fmul_rn(dx, dx);
        if (dx2 < p.w) {
#pragma unroll
            for (int q = 0; q < RPT; q++) {
                const float yf = y0f + (float)q;
                const float dy = __fsub_rn(yf, p.y);
                const float d2 = __fadd_rn(dx2, __fmul_rn(dy, dy));
                const float v  = p.z - fsqrt_approx(p.w - d2);
                if (d2 < p.w) best[q] = fminf(best[q], v);
            }
        }
    }

    float* dout = depth_out + blk * (IMG * IMG) + y0 * IMG + x;
#pragma unroll
    for (int q = 0; q < RPT; q++) {
        dout[q * IMG] = best[q];
    }
}

extern "C" void kernel_launch(void* const* d_in, const int* in_sizes, int n_in,
                              void* d_out, int out_size)
{
    const float* cam    = (const float*)d_in[0];
    const float* inv    = (const float*)d_in[1];
    const float* joints = (const float*)d_in[2];
    const float* rads   = (const float*)d_in[3];

    float* depth = (float*)d_out;                                // 8*4*4*128*128
    float* proj  = depth + (size_t)B_ * V_ * V_ * IMG * IMG;     // + 8*4*4*21*3

    const int grid = B_ * V_ * V_ * SPLIT;   // 1024
    mutual_projection_kernel<<<grid, 256>>>(cam, inv, joints, rads, depth, proj);
}

// round 10
// speedup vs baseline: 1.2731x; 1.0295x over previous
#include <cuda_runtime.h>

// MutualProjection: B=8, V=4, J=21, IMG=128
// out = [depth_imgs (B,V,V,128,128) f32][proj (B,V,V,J,3,1) f32]
// R9 skeleton + packed f32x2 math in the ball body (rn-identical per lane).

#define IMG     128
#define BIGV    1000000.0f
#define B_      8
#define V_      4
#define J_      21
#define SPLIT   8                 // row-bands per image (16 rows per CTA)
#define RPT     8                 // consecutive rows per thread

typedef unsigned long long u64;

__device__ __forceinline__ float fsqrt_approx(float a) {
    float r;
    asm("sqrt.approx.f32 %0, %1;" : "=f"(r) : "f"(a));
    return r;
}
__device__ __forceinline__ u64 pack2(float lo, float hi) {
    u64 r; asm("mov.b64 %0, {%1, %2};" : "=l"(r) : "f"(lo), "f"(hi)); return r;
}
__device__ __forceinline__ void unpack2(u64 v, float& lo, float& hi) {
    asm("mov.b64 {%0, %1}, %2;" : "=f"(lo), "=f"(hi) : "l"(v));
}
__device__ __forceinline__ u64 add2(u64 a, u64 b) {
    u64 r; asm("add.rn.f32x2 %0, %1, %2;" : "=l"(r) : "l"(a), "l"(b)); return r;
}
__device__ __forceinline__ u64 mul2(u64 a, u64 b) {
    u64 r; asm("mul.rn.f32x2 %0, %1, %2;" : "=l"(r) : "l"(a), "l"(b)); return r;
}
__device__ __forceinline__ u64 fma2(u64 a, u64 b, u64 c) {
    u64 r; asm("fma.rn.f32x2 %0, %1, %2, %3;" : "=l"(r) : "l"(a), "l"(b), "l"(c)); return r;
}

__global__ __launch_bounds__(256)
void mutual_projection_kernel(
    const float* __restrict__ cam,     // (B,V,4,4)
    const float* __restrict__ inv,     // (B,V,4,4)
    const float* __restrict__ joints,  // (B,V,J,3)
    const float* __restrict__ rads,    // (J)
    float* __restrict__ depth_out,     // (B,V,V,128,128)
    float* __restrict__ proj_out)      // (B,V,V,J,3)
{
    __shared__ float4 blist[2][J_];    // per-band compacted {px,py,pz,r2}
    __shared__ int    bcnt[2];

    const int blk = blockIdx.x >> 3;   // image index in [0,128)
    const int s   = blockIdx.x & 7;    // 16-row band
    const int b   = blk >> 4;
    const int i   = (blk >> 2) & 3;
    const int j   = blk & 3;
    const int t   = threadIdx.x;
    const int w   = t >> 5;
    const int lane = t & 31;

    // ---- Prologue: warps 0 and 1 each build the compacted ball list for
    //      their band using only intra-warp communication. One CTA barrier.
    if (w < 2) {
        const float* camM = cam + ((b * V_ + i) << 4);
        const float* invM = inv + ((b * V_ + j) << 4);

        float acc = 0.0f;
        if (lane < 12) {
            const int x = lane >> 2, z = lane & 3;
            acc =              invM[x * 4 + 0] * camM[0 * 4 + z];
            acc = fmaf(invM[x * 4 + 1], camM[1 * 4 + z], acc);
            acc = fmaf(invM[x * 4 + 2], camM[2 * 4 + z], acc);
            acc = fmaf(invM[x * 4 + 3], camM[3 * 4 + z], acc);
        }
        const unsigned FULL = 0xFFFFFFFFu;
        const float m0  = __shfl_sync(FULL, acc, 0);
        const float m1  = __shfl_sync(FULL, acc, 1);
        const float m2  = __shfl_sync(FULL, acc, 2);
        const float m3  = __shfl_sync(FULL, acc, 3);
        const float m4  = __shfl_sync(FULL, acc, 4);
        const float m5  = __shfl_sync(FULL, acc, 5);
        const float m6  = __shfl_sync(FULL, acc, 6);
        const float m7  = __shfl_sync(FULL, acc, 7);
        const float m8  = __shfl_sync(FULL, acc, 8);
        const float m9  = __shfl_sync(FULL, acc, 9);
        const float m10 = __shfl_sync(FULL, acc, 10);
        const float m11 = __shfl_sync(FULL, acc, 11);

        bool pass = false;
        float qx = 0.f, qy = 0.f, qz = 0.f, r2 = 0.f;
        if (lane < J_) {
            const float* jp = joints + ((b * V_ + i) * J_ + lane) * 3;
            const float jx = jp[0], jy = jp[1], jz = jp[2];
            qx = fmaf(m2,  jz, fmaf(m1, jy, m0 * jx)) + m3;
            qy = fmaf(m6,  jz, fmaf(m5, jy, m4 * jx)) + m7;
            qz = fmaf(m10, jz, fmaf(m9, jy, m8 * jx)) + m11;
            const float r = rads[lane];
            r2 = r * r;
            if (w == 0 && s == 0) {
                float* po = proj_out + (blk * J_ + lane) * 3;
                po[0] = qx; po[1] = qy; po[2] = qz;
            }
            // band center = y0 + 3.5; +0.01 safety so rounding never culls
            // a true-inside pixel.
            const float yc = (float)(s * 16 + w * 8) + 3.5f;
            pass = fabsf(qy - yc) < r + 3.51f;
        }
        const unsigned mask = __ballot_sync(FULL, pass);
        if (pass) {
            const int pos = __popc(mask & ((1u << lane) - 1u));
            blist[w][pos] = make_float4(qx, qy, qz, r2);
        }
        if (lane == 0) bcnt[w] = __popc(mask);
    }
    __syncthreads();

    // ---- Rasterize: warp tile = 32 cols x 8 consecutive rows.
    const int tb  = w >> 2;
    const int x   = ((w & 3) << 5) | lane;
    const int y0  = (s << 4) + (tb << 3);
    const float xf  = (float)x;
    const float y0f = (float)y0;

    // packed row coordinates (exact small ints) and constant -1 pair
    u64 yfp[RPT / 2];
#pragma unroll
    for (int h = 0; h < RPT / 2; h++)
        yfp[h] = pack2(y0f + (float)(2 * h), y0f + (float)(2 * h + 1));
    const u64 negone2 = pack2(-1.0f, -1.0f);

    float best[RPT];
#pragma unroll
    for (int q = 0; q < RPT; q++) best[q] = BIGV;

    const int cnt = bcnt[tb];
    int n = 0;
    for (; n + 1 < cnt; n += 2) {
        const float4 p0 = blist[tb][n];
        const float4 p1 = blist[tb][n + 1];

        const float dxa  = __fsub_rn(xf, p0.x);
        const float dx2a = __fmul_rn(dxa, dxa);
        const float dxb  = __fsub_rn(xf, p1.x);
        const float dx2b = __fmul_rn(dxb, dxb);

        if (dx2a < p0.w) {
            const u64 npy = pack2(-p0.y, -p0.y);   // negate exact (sign flip)
            const u64 dxp = pack2(dx2a, dx2a);
            const u64 r2p = pack2(p0.w, p0.w);
#pragma unroll
            for (int h = 0; h < RPT / 2; h++) {
                const u64 dy  = add2(yfp[h], npy);      // rn(yf - py)
                const u64 dy2 = mul2(dy, dy);           // rn(dy*dy)
                const u64 d2  = add2(dxp, dy2);         // rn(dx2 + dy2)
                const u64 ar  = fma2(d2, negone2, r2p); // rn(r2 - d2), single-round
                float a0, a1; unpack2(ar, a0, a1);
                const float v0 = p0.z - fsqrt_approx(a0);
                const float v1 = p0.z - fsqrt_approx(a1);
                if (a0 > 0.0f) best[2 * h]     = fminf(best[2 * h],     v0);
                if (a1 > 0.0f) best[2 * h + 1] = fminf(best[2 * h + 1], v1);
            }
        }
        if (dx2b < p1.w) {
            const u64 npy = pack2(-p1.y, -p1.y);
            const u64 dxp = pack2(dx2b, dx2b);
            const u64 r2p = pack2(p1.w, p1.w);
#pragma unroll
            for (int h = 0; h < RPT / 2; h++) {
                const u64 dy  = add2(yfp[h], npy);
                const u64 dy2 = mul2(dy, dy);
                const u64 d2  = add2(dxp, dy2);
                const u64 ar  = fma2(d2, negone2, r2p);
                float a0, a1; unpack2(ar, a0, a1);
                const float v0 = p1.z - fsqrt_approx(a0);
                const float v1 = p1.z - fsqrt_approx(a1);
                if (a0 > 0.0f) best[2 * h]     = fminf(best[2 * h],     v0);
                if (a1 > 0.0f) best[2 * h + 1] = fminf(best[2 * h + 1], v1);
            }
        }
    }
    if (n < cnt) {
        const float4 p  = blist[tb][n];
        const float dx  = __fsub_rn(xf, p.x);
        const float dx2 = __fmul_rn(dx, dx);
        if (dx2 < p.w) {
            const u64 npy = pack2(-p.y, -p.y);
            const u64 dxp = pack2(dx2, dx2);
            const u64 r2p = pack2(p.w, p.w);
#pragma unroll
            for (int h = 0; h < RPT / 2; h++) {
                const u64 dy  = add2(yfp[h], npy);
                const u64 dy2 = mul2(dy, dy);
                const u64 d2  = add2(dxp, dy2);
                const u64 ar  = fma2(d2, negone2, r2p);
                float a0, a1; unpack2(ar, a0, a1);
                const float v0 = p.z - fsqrt_approx(a0);
                const float v1 = p.z - fsqrt_approx(a1);
                if (a0 > 0.0f) best[2 * h]     = fminf(best[2 * h],     v0);
                if (a1 > 0.0f) best[2 * h + 1] = fminf(best[2 * h + 1], v1);
            }
        }
    }

    float* dout = depth_out + blk * (IMG * IMG) + y0 * IMG + x;
#pragma unroll
    for (int q = 0; q < RPT; q++) {
        dout[q * IMG] = best[q];
    }
}

extern "C" void kernel_launch(void* const* d_in, const int* in_sizes, int n_in,
                              void* d_out, int out_size)
{
    const float* cam    = (const float*)d_in[0];
    const float* inv    = (const float*)d_in[1];
    const float* joints = (const float*)d_in[2];
    const float* rads   = (const float*)d_in[3];

    float* depth = (float*)d_out;                                // 8*4*4*128*128
    float* proj  = depth + (size_t)B_ * V_ * V_ * IMG * IMG;     // + 8*4*4*21*3

    const int grid = B_ * V_ * V_ * SPLIT;   // 1024
    mutual_projection_kernel<<<grid, 256>>>(cam, inv, joints, rads, depth, proj);
}